// round 15
// baseline (speedup 1.0000x reference)
#include <cuda_runtime.h>
#include <cuda_bf16.h>
#include <cstdint>

// Performer (FAVOR+) causal attention — mma.sync (HMMA) implementation.
// B=8, N=4096, D=256, M=256, DV=256. Chunk C=128, NC=32.
//
// out = (tril(Pq Pk^T) V + Pq S_pre) / (rowsum(tril(Pq Pk^T)) + Pq z_pre)
// phi(x) = exp(proj - rowmax(proj))/16
//
// phi: 3xBF16 split (m16n8k16), W pre-split in gmem, 512 threads/CTA
// (16 warps -> 4 per SMSP) for issue overlap; K-side CTAs fuse z sums.
// Downstream MMAs tf32 (phi stored tf32-rounded; V fed raw). chunk kernel
// fuses Phase A (QK^T) + Phase I (Q@S_pre + den) in one k-loop, then A@V.

#define BATCH 8
#define SEQ   4096
#define DD    256
#define MM    256
#define DVV   256
#define CHUNK 128
#define NCHUNK 32

__device__ float    g_phiQ[BATCH * SEQ * MM];
__device__ float    g_phiK[BATCH * SEQ * MM];
__device__ float    g_S   [BATCH * NCHUNK * MM * DVV];   // [bc][m][dv]
__device__ float    g_z   [BATCH * NCHUNK * MM];
__device__ uint32_t g_Wh  [256 * 128];                   // W bf16-hi, k-interleaved u32
__device__ uint32_t g_Wl  [256 * 128];                   // W bf16-lo residual

__device__ __forceinline__ uint32_t su32(const void* p) {
    uint32_t a;
    asm("{ .reg .u64 t; cvta.to.shared.u64 t, %1; cvt.u32.u64 %0, t; }" : "=r"(a) : "l"(p));
    return a;
}
__device__ __forceinline__ void cpa(uint32_t d, const void* s) {
    asm volatile("cp.async.cg.shared.global [%0], [%1], 16;" :: "r"(d), "l"(s));
}
#define CP_COMMIT() asm volatile("cp.async.commit_group;" ::: "memory")
#define CP_WAIT1()  asm volatile("cp.async.wait_group 1;" ::: "memory")
#define CP_WAIT0()  asm volatile("cp.async.wait_group 0;" ::: "memory")

__device__ __forceinline__ float tf32r(float x) {
    uint32_t h; asm("cvt.rna.tf32.f32 %0, %1;" : "=r"(h) : "f"(x));
    return __uint_as_float(h);
}
__device__ __forceinline__ void mma8(float* c, const uint32_t* a, const uint32_t* b) {
    asm volatile(
        "mma.sync.aligned.m16n8k8.row.col.f32.tf32.tf32.f32 "
        "{%0,%1,%2,%3},{%4,%5,%6,%7},{%8,%9},{%0,%1,%2,%3};"
        : "+f"(c[0]), "+f"(c[1]), "+f"(c[2]), "+f"(c[3])
        : "r"(a[0]), "r"(a[1]), "r"(a[2]), "r"(a[3]), "r"(b[0]), "r"(b[1]));
}
__device__ __forceinline__ void mma16(float* c, const uint32_t* a, const uint32_t* b) {
    asm volatile(
        "mma.sync.aligned.m16n8k16.row.col.f32.bf16.bf16.f32 "
        "{%0,%1,%2,%3},{%4,%5,%6,%7},{%8,%9},{%0,%1,%2,%3};"
        : "+f"(c[0]), "+f"(c[1]), "+f"(c[2]), "+f"(c[3])
        : "r"(a[0]), "r"(a[1]), "r"(a[2]), "r"(a[3]), "r"(b[0]), "r"(b[1]));
}
__device__ __forceinline__ uint32_t fb(float x) { return __float_as_uint(x); }

__device__ __forceinline__ void split_pack(float x0, float x1, uint32_t& hp, uint32_t& lp) {
    __nv_bfloat16 h0 = __float2bfloat16_rn(x0);
    __nv_bfloat16 h1 = __float2bfloat16_rn(x1);
    float f0 = __bfloat162float(h0), f1 = __bfloat162float(h1);
    __nv_bfloat16 l0 = __float2bfloat16_rn(x0 - f0);
    __nv_bfloat16 l1 = __float2bfloat16_rn(x1 - f1);
    hp = ((uint32_t)__bfloat16_as_ushort(h1) << 16) | __bfloat16_as_ushort(h0);
    lp = ((uint32_t)__bfloat16_as_ushort(l1) << 16) | __bfloat16_as_ushort(l0);
}

// ---------------------------------------------------------------------------
// Kernel 0: pre-split W into bf16 hi/lo, k-interleaved (u0,u4,u1,u5,u2,u6,u3,u7)
// ---------------------------------------------------------------------------
__global__ void __launch_bounds__(256) wsplit(const float* __restrict__ W)
{
    const int g = blockIdx.x * 256 + threadIdx.x;
    const int row = g >> 4, grp = g & 15;
    const float* src = W + row * 256 + grp * 16;
    float4 f0 = *(const float4*)(src);
    float4 f1 = *(const float4*)(src + 4);
    float4 f2 = *(const float4*)(src + 8);
    float4 f3 = *(const float4*)(src + 12);
    uint32_t h[8], l[8];
    split_pack(f0.x, f0.y, h[0], l[0]); split_pack(f0.z, f0.w, h[1], l[1]);
    split_pack(f1.x, f1.y, h[2], l[2]); split_pack(f1.z, f1.w, h[3], l[3]);
    split_pack(f2.x, f2.y, h[4], l[4]); split_pack(f2.z, f2.w, h[5], l[5]);
    split_pack(f3.x, f3.y, h[6], l[6]); split_pack(f3.z, f3.w, h[7], l[7]);
    *(uint4*)(g_Wh + row * 128 + grp * 8)     = make_uint4(h[0], h[4], h[1], h[5]);
    *(uint4*)(g_Wh + row * 128 + grp * 8 + 4) = make_uint4(h[2], h[6], h[3], h[7]);
    *(uint4*)(g_Wl + row * 128 + grp * 8)     = make_uint4(l[0], l[4], l[1], l[5]);
    *(uint4*)(g_Wl + row * 128 + grp * 8 + 4) = make_uint4(l[2], l[6], l[3], l[7]);
}

// ---------------------------------------------------------------------------
// Kernel 1: phi = exp(X @ W^T - rowmax)/16, 3xBF16 (m16n8k16), 512 threads.
// grid 512 (bid<256 -> Q else K_in). 16 warps: wm<4 (32-row), wn<4 (64-col).
// K-side CTAs also emit g_z (fused zsum).
// ---------------------------------------------------------------------------
#define PHI_SMEM ((3072 + 3072 + 6144 + 6144 + 512 + 1024) * 4)

__global__ void __launch_bounds__(512) phi_mma(const float* __restrict__ Q,
                                               const float* __restrict__ Kin)
{
    extern __shared__ uint32_t smu[];
    uint32_t* Xh = smu;              // 2 bufs * 128*12
    uint32_t* Xl = Xh + 3072;
    uint32_t* Wh = Xl + 3072;        // 2 bufs * 256*12
    uint32_t* Wl = Wh + 6144;
    float* rmax = (float*)(Wl + 6144);   // 512: [wn][row]
    float* zwp  = rmax + 512;            // 4*256
    const uint32_t whb = su32(Wh), wlb = su32(Wl);

    const int tid = threadIdx.x;
    const int lane = tid & 31, w = tid >> 5;
    const int gid = lane >> 2, tig = lane & 3;
    const int wm = w >> 2, wn = w & 3;

    const int bid = blockIdx.x;
    const float* X = (bid < 256) ? Q : Kin;
    float* Phi = (bid < 256) ? g_phiQ : g_phiK;
    const size_t row0 = (size_t)(bid & 255) * 128;

    float acc[2][8][4];
#pragma unroll
    for (int mt = 0; mt < 2; mt++)
#pragma unroll
        for (int nt = 0; nt < 8; nt++)
#pragma unroll
            for (int i = 0; i < 4; i++) acc[mt][nt][i] = 0.f;

    const int xr = tid >> 2, xq = tid & 3;
    const int s0 = (xq < 2) ? (4 * xq) : (4 * xq - 7);   // k-interleave slot
    const float* xsrc = X + (row0 + xr) * DD + xq * 4;

    float4 rx;

#define PHI_LD(st) { rx = *(const float4*)(xsrc + (st) * 16); }

#define PHI_STX(bf) { \
    uint32_t* dxh = Xh + (bf) * 1536 + xr * 12 + s0; \
    uint32_t* dxl = Xl + (bf) * 1536 + xr * 12 + s0; \
    uint32_t hh, ll; \
    split_pack(rx.x, rx.y, hh, ll); dxh[0] = hh; dxl[0] = ll; \
    split_pack(rx.z, rx.w, hh, ll); dxh[2] = hh; dxl[2] = ll; }

#define W_CP(st, bf) { \
    const int r = tid >> 1, part = (tid & 1) * 4; \
    cpa(whb + (((bf) * 3072) + r * 12 + part) * 4, g_Wh + r * 128 + (st) * 8 + part); \
    cpa(wlb + (((bf) * 3072) + r * 12 + part) * 4, g_Wl + r * 128 + (st) * 8 + part); \
    CP_COMMIT(); }

    PHI_LD(0);
    W_CP(0, 0);
    PHI_STX(0);

#pragma unroll 1
    for (int st = 0; st < 16; st++) {
        const int buf = st & 1;
        if (st < 15) { PHI_LD(st + 1); W_CP(st + 1, buf ^ 1); CP_WAIT1(); }
        else         { CP_WAIT0(); }
        __syncthreads();

        const uint32_t* xh = Xh + buf * 1536;
        const uint32_t* xl = Xl + buf * 1536;
        const uint32_t* wh = Wh + buf * 3072;
        const uint32_t* wl = Wl + buf * 3072;

        uint32_t ah[2][4], al[2][4];
#pragma unroll
        for (int mt = 0; mt < 2; mt++) {
            const int rb = wm * 32 + mt * 16;
            uint2 v;
            v = *(const uint2*)(&xh[(rb + gid) * 12 + 2 * tig]);
            ah[mt][0] = v.x; ah[mt][2] = v.y;
            v = *(const uint2*)(&xh[(rb + gid + 8) * 12 + 2 * tig]);
            ah[mt][1] = v.x; ah[mt][3] = v.y;
            v = *(const uint2*)(&xl[(rb + gid) * 12 + 2 * tig]);
            al[mt][0] = v.x; al[mt][2] = v.y;
            v = *(const uint2*)(&xl[(rb + gid + 8) * 12 + 2 * tig]);
            al[mt][1] = v.x; al[mt][3] = v.y;
        }
#pragma unroll
        for (int nt = 0; nt < 8; nt++) {
            const int nb = wn * 64 + nt * 8;
            uint2 bh2 = *(const uint2*)(&wh[(nb + gid) * 12 + 2 * tig]);
            uint2 bl2 = *(const uint2*)(&wl[(nb + gid) * 12 + 2 * tig]);
            uint32_t bh[2] = { bh2.x, bh2.y };
            uint32_t bl[2] = { bl2.x, bl2.y };
            mma16(acc[0][nt], ah[0], bh);
            mma16(acc[1][nt], ah[1], bh);
            mma16(acc[0][nt], ah[0], bl);
            mma16(acc[1][nt], ah[1], bl);
            mma16(acc[0][nt], al[0], bh);
            mma16(acc[1][nt], al[1], bh);
        }
        if (st < 15) PHI_STX(buf ^ 1);
        __syncthreads();
    }

    // rowmax: per-warp over its 64 cols -> rmax[wn][row], then max of 4 slices
#pragma unroll
    for (int mt = 0; mt < 2; mt++) {
        float mlo = -1e30f, mhi = -1e30f;
#pragma unroll
        for (int nt = 0; nt < 8; nt++) {
            mlo = fmaxf(mlo, fmaxf(acc[mt][nt][0], acc[mt][nt][1]));
            mhi = fmaxf(mhi, fmaxf(acc[mt][nt][2], acc[mt][nt][3]));
        }
        mlo = fmaxf(mlo, __shfl_xor_sync(0xffffffffu, mlo, 1));
        mlo = fmaxf(mlo, __shfl_xor_sync(0xffffffffu, mlo, 2));
        mhi = fmaxf(mhi, __shfl_xor_sync(0xffffffffu, mhi, 1));
        mhi = fmaxf(mhi, __shfl_xor_sync(0xffffffffu, mhi, 2));
        const int rl = wm * 32 + mt * 16 + gid;
        if (tig == 0) { rmax[wn * 128 + rl] = mlo; rmax[wn * 128 + rl + 8] = mhi; }
    }
    __syncthreads();

    // exp epilogue + (K-side) column-sum accumulation for fused zsum
    float zc0[8], zc1[8];
#pragma unroll
    for (int nt = 0; nt < 8; nt++) { zc0[nt] = 0.f; zc1[nt] = 0.f; }

#pragma unroll
    for (int mt = 0; mt < 2; mt++) {
        const int rl = wm * 32 + mt * 16 + gid, rh = rl + 8;
        const float Ml = fmaxf(fmaxf(rmax[rl], rmax[128 + rl]),
                               fmaxf(rmax[256 + rl], rmax[384 + rl]));
        const float Mh = fmaxf(fmaxf(rmax[rh], rmax[128 + rh]),
                               fmaxf(rmax[256 + rh], rmax[384 + rh]));
        float* pl = Phi + (row0 + rl) * MM;
        float* ph = Phi + (row0 + rh) * MM;
#pragma unroll
        for (int nt = 0; nt < 8; nt++) {
            const int col = wn * 64 + nt * 8 + tig * 2;
            float2 v0, v1;
            v0.x = tf32r(__expf(acc[mt][nt][0] - Ml) * 0.0625f);
            v0.y = tf32r(__expf(acc[mt][nt][1] - Ml) * 0.0625f);
            v1.x = tf32r(__expf(acc[mt][nt][2] - Mh) * 0.0625f);
            v1.y = tf32r(__expf(acc[mt][nt][3] - Mh) * 0.0625f);
            *(float2*)(pl + col) = v0;
            *(float2*)(ph + col) = v1;
            zc0[nt] += v0.x + v1.x;
            zc1[nt] += v0.y + v1.y;
        }
    }

    if (bid >= 256) {
#pragma unroll
        for (int nt = 0; nt < 8; nt++) {
            zc0[nt] += __shfl_xor_sync(0xffffffffu, zc0[nt], 4);
            zc0[nt] += __shfl_xor_sync(0xffffffffu, zc0[nt], 8);
            zc0[nt] += __shfl_xor_sync(0xffffffffu, zc0[nt], 16);
            zc1[nt] += __shfl_xor_sync(0xffffffffu, zc1[nt], 4);
            zc1[nt] += __shfl_xor_sync(0xffffffffu, zc1[nt], 8);
            zc1[nt] += __shfl_xor_sync(0xffffffffu, zc1[nt], 16);
            if (gid == 0) {
                const int col = wn * 64 + nt * 8 + tig * 2;
                zwp[wm * 256 + col]     = zc0[nt];
                zwp[wm * 256 + col + 1] = zc1[nt];
            }
        }
        __syncthreads();
        if (tid < 256) {
            const float zz = zwp[tid] + zwp[256 + tid] + zwp[512 + tid] + zwp[768 + tid];
            g_z[(size_t)(bid - 256) * MM + tid] = zz;
        }
    }
}

// ---------------------------------------------------------------------------
// Kernel 2: S_c[m][dv] = sum_k phiK[k][m] * V[k][dv], K=128, k16 stages,
// 35KB smem + minBlocks=2 -> 2 CTAs/SM.
// ---------------------------------------------------------------------------
#define SC_SMEM ((2*2176 + 2*2176) * 4)

__global__ void __launch_bounds__(256, 2) scontrib_mma(const float* __restrict__ V)
{
    extern __shared__ float sm[];
    float* As = sm;            // 2 * 16*136 (phiK [k][m])
    float* Bs = As + 4352;     // 2 * 16*136 (V [k][dv])
    const uint32_t asb = su32(As), bsb = su32(Bs);

    const int tid = threadIdx.x;
    const int lane = tid & 31, w = tid >> 5;
    const int gid = lane >> 2, tig = lane & 3;
    const int wm = w >> 1, wn = w & 1;

    const int bc = blockIdx.z;
    const int m0c = blockIdx.y * 128, dv0 = blockIdx.x * 128;
    const size_t base = (size_t)(bc >> 5) * SEQ + (size_t)(bc & 31) * CHUNK;
    const float* pk = g_phiK + base * MM + m0c;
    const float* vv = V + base * DVV + dv0;

    float acc[2][8][4];
#pragma unroll
    for (int mt = 0; mt < 2; mt++)
#pragma unroll
        for (int nt = 0; nt < 8; nt++)
#pragma unroll
            for (int i = 0; i < 4; i++) acc[mt][nt][i] = 0.f;

#define SC_CP(st, bf) { \
    _Pragma("unroll") \
    for (int j = 0; j < 2; j++) { \
        const int idx = tid + j * 256; \
        const int r = idx >> 5, q = (idx & 31) * 4; \
        cpa(asb + ((bf) * 2176 + r * 136 + q) * 4, pk + ((st) * 16 + r) * MM + q); \
        cpa(bsb + ((bf) * 2176 + r * 136 + q) * 4, vv + ((st) * 16 + r) * DVV + q); \
    } \
    CP_COMMIT(); }

    SC_CP(0, 0);
#pragma unroll 1
    for (int st = 0; st < 8; st++) {
        const int buf = st & 1;
        if (st < 7) { SC_CP(st + 1, buf ^ 1); CP_WAIT1(); } else { CP_WAIT0(); }
        __syncthreads();
        const float* as = As + buf * 2176;
        const float* bs = Bs + buf * 2176;
#pragma unroll
        for (int k8 = 0; k8 < 16; k8 += 8) {
            uint32_t a[2][4];
#pragma unroll
            for (int mt = 0; mt < 2; mt++) {
                const int rb = wm * 32 + mt * 16;
                a[mt][0] = fb(as[(k8 + tig) * 136 + rb + gid]);
                a[mt][1] = fb(as[(k8 + tig) * 136 + rb + gid + 8]);
                a[mt][2] = fb(as[(k8 + tig + 4) * 136 + rb + gid]);
                a[mt][3] = fb(as[(k8 + tig + 4) * 136 + rb + gid + 8]);
            }
#pragma unroll
            for (int nt = 0; nt < 8; nt++) {
                const int nb = wn * 64 + nt * 8;
                uint32_t b[2] = { fb(bs[(k8 + tig) * 136 + nb + gid]),
                                  fb(bs[(k8 + tig + 4) * 136 + nb + gid]) };
                mma8(acc[0][nt], a[0], b);
                mma8(acc[1][nt], a[1], b);
            }
        }
        __syncthreads();
    }

    float* sout = g_S + (size_t)bc * (MM * DVV);
#pragma unroll
    for (int mt = 0; mt < 2; mt++) {
        const int m = m0c + wm * 32 + mt * 16 + gid;
#pragma unroll
        for (int nt = 0; nt < 8; nt++) {
            const int col = dv0 + wn * 64 + nt * 8 + tig * 2;
            *(float2*)(sout + (size_t)m * DVV + col) =
                make_float2(acc[mt][nt][0], acc[mt][nt][1]);
            *(float2*)(sout + (size_t)(m + 8) * DVV + col) =
                make_float2(acc[mt][nt][2], acc[mt][nt][3]);
        }
    }
}

// exclusive prefixes over chunks
__global__ void __launch_bounds__(256) prefixS_kernel()
{
    const size_t g = (size_t)blockIdx.x * 256 + threadIdx.x;
    const size_t b = g >> 16, r = g & 65535;
    float* p = g_S + b * (size_t)NCHUNK * 65536 + r;
    float v[NCHUNK];
#pragma unroll
    for (int c = 0; c < NCHUNK; c++) v[c] = p[(size_t)c * 65536];
    float run = 0.f;
#pragma unroll
    for (int c = 0; c < NCHUNK; c++) { float t = v[c]; v[c] = run; run += t; }
#pragma unroll
    for (int c = 0; c < NCHUNK; c++) p[(size_t)c * 65536] = v[c];
}
__global__ void __launch_bounds__(256) prefixz_kernel()
{
    const int g = blockIdx.x * 256 + threadIdx.x;
    const int b = g / MM, m = g % MM;
    float* p = g_z + (size_t)b * NCHUNK * MM + m;
    float v[NCHUNK];
#pragma unroll
    for (int c = 0; c < NCHUNK; c++) v[c] = p[c * MM];
    float run = 0.f;
#pragma unroll
    for (int c = 0; c < NCHUNK; c++) { float t = v[c]; v[c] = run; run += t; }
#pragma unroll
    for (int c = 0; c < NCHUNK; c++) p[c * MM] = v[c];
}

// ---------------------------------------------------------------------------
// Kernel 3 (FUSED): per (b,chunk):
//   Merged Phase A+I over K=256 (shared phiQ tiles):
//     acc  = Pq Pk^T;  acc2 = Pq S_pre;  dp = den_inter FMAs
//   Epilogue: mask/round acc -> As2, rowsum -> rsh.
//   Phase B: acc2 += As2 @ V (K=128).   Out = acc2 / den.
// ---------------------------------------------------------------------------
#define CH_SMEM ((5120 + 5120 + 8448 + 16896 + 256 + 256 + 256 + 128) * 4)

__global__ void __launch_bounds__(256) chunk_fused(const float* __restrict__ V,
                                                   float* __restrict__ Out)
{
    extern __shared__ float sm[];
    float* Aq  = sm;              // 2*128*20 (phiQ tiles)
    float* Kk  = Aq + 5120;       // 2*128*20 (phiK tiles)
    float* Sp  = Kk + 5120;       // 2*16*264 (Spre tiles; later V tiles)
    float* As2 = Sp + 8448;       // 128*132
    float* zsm = As2 + 16896;     // 256
    float* rsh = zsm + 256;       // 256
    float* dps = rsh + 256;       // 256
    float* rden = dps + 256;      // 128
    const uint32_t aqb = su32(Aq), kkb = su32(Kk), spb = su32(Sp);

    const int tid = threadIdx.x;
    const int lane = tid & 31, w = tid >> 5;
    const int gid = lane >> 2, tig = lane & 3;
    const int wm = w >> 1, wn = w & 1;

    const int bc = blockIdx.x;
    const size_t base = (size_t)(bc >> 5) * SEQ + (size_t)(bc & 31) * CHUNK;
    const float* pq = g_phiQ + base * MM;
    const float* pk = g_phiK + base * MM;
    const float* Vb = V + base * DVV;
    const float* sS = g_S + (size_t)bc * (MM * DVV);

    zsm[tid] = g_z[(size_t)bc * MM + tid];

    float acc[2][8][4];
    float acc2[2][16][4];
#pragma unroll
    for (int mt = 0; mt < 2; mt++) {
#pragma unroll
        for (int nt = 0; nt < 8; nt++)
#pragma unroll
            for (int i = 0; i < 4; i++) acc[mt][nt][i] = 0.f;
#pragma unroll
        for (int nt = 0; nt < 16; nt++)
#pragma unroll
            for (int i = 0; i < 4; i++) acc2[mt][nt][i] = 0.f;
    }

#define CAI_CP(st, bf) { \
    _Pragma("unroll") \
    for (int j = 0; j < 2; j++) { \
        const int idx = tid + j * 256; \
        const int r = idx >> 2, q = (idx & 3) * 4; \
        cpa(aqb + ((bf) * 2560 + r * 20 + q) * 4, pq + r * MM + (st) * 16 + q); \
        cpa(kkb + ((bf) * 2560 + r * 20 + q) * 4, pk + r * MM + (st) * 16 + q); \
    } \
    _Pragma("unroll") \
    for (int j = 0; j < 4; j++) { \
        const int idx = tid + j * 256; \
        const int r = idx >> 6, qc = (idx & 63) * 4; \
        cpa(spb + ((bf) * 4224 + r * 264 + qc) * 4, sS + ((st) * 16 + r) * DVV + qc); \
    } \
    CP_COMMIT(); }

    float dp = 0.f;
    const int dr = tid >> 1, dh = tid & 1;

    CAI_CP(0, 0);
#pragma unroll 1
    for (int st = 0; st < 16; st++) {
        const int buf = st & 1;
        if (st < 15) { CAI_CP(st + 1, buf ^ 1); CP_WAIT1(); } else { CP_WAIT0(); }
        __syncthreads();
        const float* aq = Aq + buf * 2560;
        const float* kk = Kk + buf * 2560;
        const float* sp = Sp + buf * 4224;
#pragma unroll
        for (int k8 = 0; k8 < 16; k8 += 8) {
            uint32_t a[2][4];
#pragma unroll
            for (int mt = 0; mt < 2; mt++) {
                const int rb = wm * 32 + mt * 16;
                a[mt][0] = fb(aq[(rb + gid) * 20 + k8 + tig]);
                a[mt][1] = fb(aq[(rb + gid + 8) * 20 + k8 + tig]);
                a[mt][2] = fb(aq[(rb + gid) * 20 + k8 + tig + 4]);
                a[mt][3] = fb(aq[(rb + gid + 8) * 20 + k8 + tig + 4]);
            }
#pragma unroll
            for (int nt = 0; nt < 8; nt++) {
                const int nb = wn * 64 + nt * 8;
                uint32_t b[2] = { fb(kk[(nb + gid) * 20 + k8 + tig]),
                                  fb(kk[(nb + gid) * 20 + k8 + tig + 4]) };
                mma8(acc[0][nt], a[0], b);
                mma8(acc[1][nt], a[1], b);
            }
#pragma unroll
            for (int nt = 0; nt < 16; nt++) {
                const int nb = wn * 128 + nt * 8;
                uint32_t b[2] = { fb(sp[(k8 + tig) * 264 + nb + gid]),
                                  fb(sp[(k8 + tig + 4) * 264 + nb + gid]) };
                mma8(acc2[0][nt], a[0], b);
                mma8(acc2[1][nt], a[1], b);
            }
        }
#pragma unroll
        for (int j = 0; j < 8; j++)
            dp = fmaf(aq[dr * 20 + dh * 8 + j], zsm[st * 16 + dh * 8 + j], dp);
        __syncthreads();
    }
    dps[tid] = dp;

#define CB_CP(st, bf) { \
    _Pragma("unroll") \
    for (int j = 0; j < 4; j++) { \
        const int idx = tid + j * 256; \
        const int r = idx >> 6, qc = (idx & 63) * 4; \
        cpa(spb + ((bf) * 4224 + r * 264 + qc) * 4, Vb + ((st) * 16 + r) * DVV + qc); \
    } \
    CP_COMMIT(); }

    CB_CP(0, 0);

#pragma unroll
    for (int mt = 0; mt < 2; mt++) {
        const int row = wm * 32 + mt * 16 + gid, row2 = row + 8;
        float rs1 = 0.f, rs2 = 0.f;
#pragma unroll
        for (int nt = 0; nt < 8; nt++) {
            const int col = wn * 64 + nt * 8 + tig * 2;
            float v0 = (col     <= row)  ? tf32r(acc[mt][nt][0]) : 0.f;
            float v1 = (col + 1 <= row)  ? tf32r(acc[mt][nt][1]) : 0.f;
            float v2 = (col     <= row2) ? tf32r(acc[mt][nt][2]) : 0.f;
            float v3 = (col + 1 <= row2) ? tf32r(acc[mt][nt][3]) : 0.f;
            rs1 += v0 + v1; rs2 += v2 + v3;
            *(float2*)(As2 + row * 132 + col) = make_float2(v0, v1);
            *(float2*)(As2 + row2 * 132 + col) = make_float2(v2, v3);
        }
        rs1 += __shfl_xor_sync(0xffffffffu, rs1, 1);
        rs1 += __shfl_xor_sync(0xffffffffu, rs1, 2);
        rs2 += __shfl_xor_sync(0xffffffffu, rs2, 1);
        rs2 += __shfl_xor_sync(0xffffffffu, rs2, 2);
        if (tig == 0) { rsh[wn * 128 + row] = rs1; rsh[wn * 128 + row2] = rs2; }
    }
    __syncthreads();
    if (tid < 128)
        rden[tid] = 1.f / fmaxf(rsh[tid] + rsh[128 + tid] + dps[2 * tid] + dps[2 * tid + 1], 1e-6f);

#pragma unroll 1
    for (int st = 0; st < 8; st++) {
        const int buf = st & 1;
        if (st < 7) { CB_CP(st + 1, buf ^ 1); CP_WAIT1(); } else { CP_WAIT0(); }
        __syncthreads();
        const float* vs = Sp + buf * 4224;
#pragma unroll
        for (int k8 = 0; k8 < 16; k8 += 8) {
            const int kg = st * 16 + k8;
            uint32_t a[2][4];
#pragma unroll
            for (int mt = 0; mt < 2; mt++) {
                const int rb = wm * 32 + mt * 16;
                a[mt][0] = fb(As2[(rb + gid) * 132 + kg + tig]);
                a[mt][1] = fb(As2[(rb + gid + 8) * 132 + kg + tig]);
                a[mt][2] = fb(As2[(rb + gid) * 132 + kg + tig + 4]);
                a[mt][3] = fb(As2[(rb + gid + 8) * 132 + kg + tig + 4]);
            }
#pragma unroll
            for (int nt = 0; nt < 16; nt++) {
                const int nb = wn * 128 + nt * 8;
                uint32_t b[2] = { fb(vs[(k8 + tig) * 264 + nb + gid]),
                                  fb(vs[(k8 + tig + 4) * 264 + nb + gid]) };
                mma8(acc2[0][nt], a[0], b);
                mma8(acc2[1][nt], a[1], b);
            }
        }
        __syncthreads();
    }

#pragma unroll
    for (int mt = 0; mt < 2; mt++) {
        const int t = wm * 32 + mt * 16 + gid, t2 = t + 8;
        const float r1 = rden[t], r2 = rden[t2];
#pragma unroll
        for (int nt = 0; nt < 16; nt++) {
            const int col = wn * 128 + nt * 8 + tig * 2;
            *(float2*)(Out + (base + t) * DVV + col) =
                make_float2(acc2[mt][nt][0] * r1, acc2[mt][nt][1] * r1);
            *(float2*)(Out + (base + t2) * DVV + col) =
                make_float2(acc2[mt][nt][2] * r2, acc2[mt][nt][3] * r2);
        }
    }
}

// ---------------------------------------------------------------------------
extern "C" void kernel_launch(void* const* d_in, const int* in_sizes, int n_in,
                              void* d_out, int out_size)
{
    (void)in_sizes; (void)n_in; (void)out_size;
    const float* Q   = (const float*)d_in[0];
    const float* Kin = (const float*)d_in[1];
    const float* V   = (const float*)d_in[2];
    const float* W   = (const float*)d_in[3];
    float* Out = (float*)d_out;

    cudaFuncSetAttribute(phi_mma,      cudaFuncAttributeMaxDynamicSharedMemorySize, PHI_SMEM);
    cudaFuncSetAttribute(scontrib_mma, cudaFuncAttributeMaxDynamicSharedMemorySize, SC_SMEM);
    cudaFuncSetAttribute(chunk_fused,  cudaFuncAttributeMaxDynamicSharedMemorySize, CH_SMEM);

    wsplit<<<16, 256>>>(W);
    phi_mma<<<512, 512, PHI_SMEM>>>(Q, Kin);
    prefixz_kernel<<<(BATCH * MM) / 256, 256>>>();
    scontrib_mma<<<dim3(2, 2, BATCH * NCHUNK), 256, SC_SMEM>>>(V);
    prefixS_kernel<<<(BATCH * MM * DVV) / 256, 256>>>();
    chunk_fused<<<BATCH * NCHUNK, 256, CH_SMEM>>>(V, Out);
}

// round 16
// speedup vs baseline: 1.0316x; 1.0316x over previous
#include <cuda_runtime.h>
#include <cuda_bf16.h>
#include <cstdint>

// Performer (FAVOR+) causal attention — mma.sync (HMMA) implementation.
// B=8, N=4096, D=256, M=256, DV=256. Chunk C=128, NC=32.
//
// out = (tril(Pq Pk^T) V + Pq S_pre) / (rowsum(tril(Pq Pk^T)) + Pq z_pre)
// phi(x) = exp(proj - rowmax(proj))/16
//
// phi: 3xBF16 split (m16n8k16), W pre-split in gmem; K-side CTAs fuse z sums.
// Downstream MMAs tf32 (phi stored tf32-rounded; V fed raw). chunk kernel
// fuses Phase A (QK^T) + Phase I (Q@S_pre + den) in one k-loop, then A@V.
// phi and chunk use DEPTH-3 cp.async pipelines to hide memory latency.

#define BATCH 8
#define SEQ   4096
#define DD    256
#define MM    256
#define DVV   256
#define CHUNK 128
#define NCHUNK 32

__device__ float    g_phiQ[BATCH * SEQ * MM];
__device__ float    g_phiK[BATCH * SEQ * MM];
__device__ float    g_S   [BATCH * NCHUNK * MM * DVV];   // [bc][m][dv]
__device__ float    g_z   [BATCH * NCHUNK * MM];
__device__ uint32_t g_Wh  [256 * 128];                   // W bf16-hi, k-interleaved u32
__device__ uint32_t g_Wl  [256 * 128];                   // W bf16-lo residual

__device__ __forceinline__ uint32_t su32(const void* p) {
    uint32_t a;
    asm("{ .reg .u64 t; cvta.to.shared.u64 t, %1; cvt.u32.u64 %0, t; }" : "=r"(a) : "l"(p));
    return a;
}
__device__ __forceinline__ void cpa(uint32_t d, const void* s) {
    asm volatile("cp.async.cg.shared.global [%0], [%1], 16;" :: "r"(d), "l"(s));
}
#define CP_COMMIT() asm volatile("cp.async.commit_group;" ::: "memory")
#define CP_WAIT2()  asm volatile("cp.async.wait_group 2;" ::: "memory")
#define CP_WAIT1()  asm volatile("cp.async.wait_group 1;" ::: "memory")
#define CP_WAIT0()  asm volatile("cp.async.wait_group 0;" ::: "memory")

__device__ __forceinline__ float tf32r(float x) {
    uint32_t h; asm("cvt.rna.tf32.f32 %0, %1;" : "=r"(h) : "f"(x));
    return __uint_as_float(h);
}
__device__ __forceinline__ void mma8(float* c, const uint32_t* a, const uint32_t* b) {
    asm volatile(
        "mma.sync.aligned.m16n8k8.row.col.f32.tf32.tf32.f32 "
        "{%0,%1,%2,%3},{%4,%5,%6,%7},{%8,%9},{%0,%1,%2,%3};"
        : "+f"(c[0]), "+f"(c[1]), "+f"(c[2]), "+f"(c[3])
        : "r"(a[0]), "r"(a[1]), "r"(a[2]), "r"(a[3]), "r"(b[0]), "r"(b[1]));
}
__device__ __forceinline__ void mma16(float* c, const uint32_t* a, const uint32_t* b) {
    asm volatile(
        "mma.sync.aligned.m16n8k16.row.col.f32.bf16.bf16.f32 "
        "{%0,%1,%2,%3},{%4,%5,%6,%7},{%8,%9},{%0,%1,%2,%3};"
        : "+f"(c[0]), "+f"(c[1]), "+f"(c[2]), "+f"(c[3])
        : "r"(a[0]), "r"(a[1]), "r"(a[2]), "r"(a[3]), "r"(b[0]), "r"(b[1]));
}
__device__ __forceinline__ uint32_t fb(float x) { return __float_as_uint(x); }

__device__ __forceinline__ void split_pack(float x0, float x1, uint32_t& hp, uint32_t& lp) {
    __nv_bfloat16 h0 = __float2bfloat16_rn(x0);
    __nv_bfloat16 h1 = __float2bfloat16_rn(x1);
    float f0 = __bfloat162float(h0), f1 = __bfloat162float(h1);
    __nv_bfloat16 l0 = __float2bfloat16_rn(x0 - f0);
    __nv_bfloat16 l1 = __float2bfloat16_rn(x1 - f1);
    hp = ((uint32_t)__bfloat16_as_ushort(h1) << 16) | __bfloat16_as_ushort(h0);
    lp = ((uint32_t)__bfloat16_as_ushort(l1) << 16) | __bfloat16_as_ushort(l0);
}

// ---------------------------------------------------------------------------
// Kernel 0: pre-split W into bf16 hi/lo, k-interleaved (u0,u4,u1,u5,u2,u6,u3,u7)
// ---------------------------------------------------------------------------
__global__ void __launch_bounds__(256) wsplit(const float* __restrict__ W)
{
    const int g = blockIdx.x * 256 + threadIdx.x;
    const int row = g >> 4, grp = g & 15;
    const float* src = W + row * 256 + grp * 16;
    float4 f0 = *(const float4*)(src);
    float4 f1 = *(const float4*)(src + 4);
    float4 f2 = *(const float4*)(src + 8);
    float4 f3 = *(const float4*)(src + 12);
    uint32_t h[8], l[8];
    split_pack(f0.x, f0.y, h[0], l[0]); split_pack(f0.z, f0.w, h[1], l[1]);
    split_pack(f1.x, f1.y, h[2], l[2]); split_pack(f1.z, f1.w, h[3], l[3]);
    split_pack(f2.x, f2.y, h[4], l[4]); split_pack(f2.z, f2.w, h[5], l[5]);
    split_pack(f3.x, f3.y, h[6], l[6]); split_pack(f3.z, f3.w, h[7], l[7]);
    *(uint4*)(g_Wh + row * 128 + grp * 8)     = make_uint4(h[0], h[4], h[1], h[5]);
    *(uint4*)(g_Wh + row * 128 + grp * 8 + 4) = make_uint4(h[2], h[6], h[3], h[7]);
    *(uint4*)(g_Wl + row * 128 + grp * 8)     = make_uint4(l[0], l[4], l[1], l[5]);
    *(uint4*)(g_Wl + row * 128 + grp * 8 + 4) = make_uint4(l[2], l[6], l[3], l[7]);
}

// ---------------------------------------------------------------------------
// Kernel 1: phi = exp(X @ W^T - rowmax)/16, 3xBF16 (m16n8k16), depth-3 pipe.
// grid 512 (bid<256 -> Q else K_in). K-side CTAs also emit g_z (fused zsum).
// ---------------------------------------------------------------------------
#define PHI_SMEM ((3*1536*2 + 3*3072*2 + 256 + 1024) * 4)

__global__ void __launch_bounds__(256) phi_mma(const float* __restrict__ Q,
                                               const float* __restrict__ Kin)
{
    extern __shared__ uint32_t smu[];
    uint32_t* Xh = smu;              // 3 bufs * 128*12
    uint32_t* Xl = Xh + 4608;
    uint32_t* Wh = Xl + 4608;        // 3 bufs * 256*12
    uint32_t* Wl = Wh + 9216;
    float* rmax = (float*)(Wl + 9216);   // 256
    float* zwp  = rmax + 256;            // 4*256
    const uint32_t whb = su32(Wh), wlb = su32(Wl);

    const int tid = threadIdx.x;
    const int lane = tid & 31, w = tid >> 5;
    const int gid = lane >> 2, tig = lane & 3;
    const int wm = w >> 1, wn = w & 1;

    const int bid = blockIdx.x;
    const float* X = (bid < 256) ? Q : Kin;
    float* Phi = (bid < 256) ? g_phiQ : g_phiK;
    const size_t row0 = (size_t)(bid & 255) * 128;

    float acc[2][16][4];
#pragma unroll
    for (int mt = 0; mt < 2; mt++)
#pragma unroll
        for (int nt = 0; nt < 16; nt++)
#pragma unroll
            for (int i = 0; i < 4; i++) acc[mt][nt][i] = 0.f;

    const int xr = tid >> 1, xhalf = tid & 1;
    const float* xsrc = X + (row0 + xr) * DD + xhalf * 8;

    float4 rx0, rx1;

#define PHI_LD(st) { \
    rx0 = *(const float4*)(xsrc + (st) * 16); \
    rx1 = *(const float4*)(xsrc + (st) * 16 + 4); }

#define PHI_STX(bf) { \
    uint32_t* dxh = Xh + (bf) * 1536 + xr * 12 + xhalf; \
    uint32_t* dxl = Xl + (bf) * 1536 + xr * 12 + xhalf; \
    uint32_t hh, ll; \
    split_pack(rx0.x, rx0.y, hh, ll); dxh[0] = hh; dxl[0] = ll; \
    split_pack(rx0.z, rx0.w, hh, ll); dxh[2] = hh; dxl[2] = ll; \
    split_pack(rx1.x, rx1.y, hh, ll); dxh[4] = hh; dxl[4] = ll; \
    split_pack(rx1.z, rx1.w, hh, ll); dxh[6] = hh; dxl[6] = ll; }

#define W_CP(st, bf) { \
    _Pragma("unroll") \
    for (int j = 0; j < 2; j++) { \
        const int idx = tid + j * 256; \
        const int r = idx >> 1, part = (idx & 1) * 4; \
        cpa(whb + (((bf) * 3072) + r * 12 + part) * 4, g_Wh + r * 128 + (st) * 8 + part); \
        cpa(wlb + (((bf) * 3072) + r * 12 + part) * 4, g_Wl + r * 128 + (st) * 8 + part); \
    } \
    CP_COMMIT(); }

    // prologue: stages 0 and 1 in flight
    PHI_LD(0); PHI_STX(0); W_CP(0, 0);
    PHI_LD(1); PHI_STX(1); W_CP(1, 1);

#pragma unroll 1
    for (int st = 0; st < 16; st++) {
        const int buf = st % 3;
        if (st < 14) { PHI_LD(st + 2); W_CP(st + 2, (st + 2) % 3); CP_WAIT2(); }
        else if (st == 14) { CP_WAIT1(); }
        else { CP_WAIT0(); }
        __syncthreads();

        const uint32_t* xh = Xh + buf * 1536;
        const uint32_t* xl = Xl + buf * 1536;
        const uint32_t* wh = Wh + buf * 3072;
        const uint32_t* wl = Wl + buf * 3072;

        uint32_t ah[2][4], al[2][4];
#pragma unroll
        for (int mt = 0; mt < 2; mt++) {
            const int rb = wm * 32 + mt * 16;
            uint2 v;
            v = *(const uint2*)(&xh[(rb + gid) * 12 + 2 * tig]);
            ah[mt][0] = v.x; ah[mt][2] = v.y;
            v = *(const uint2*)(&xh[(rb + gid + 8) * 12 + 2 * tig]);
            ah[mt][1] = v.x; ah[mt][3] = v.y;
            v = *(const uint2*)(&xl[(rb + gid) * 12 + 2 * tig]);
            al[mt][0] = v.x; al[mt][2] = v.y;
            v = *(const uint2*)(&xl[(rb + gid + 8) * 12 + 2 * tig]);
            al[mt][1] = v.x; al[mt][3] = v.y;
        }
#pragma unroll
        for (int nt = 0; nt < 16; nt++) {
            const int nb = wn * 128 + nt * 8;
            uint2 bh2 = *(const uint2*)(&wh[(nb + gid) * 12 + 2 * tig]);
            uint2 bl2 = *(const uint2*)(&wl[(nb + gid) * 12 + 2 * tig]);
            uint32_t bh[2] = { bh2.x, bh2.y };
            uint32_t bl[2] = { bl2.x, bl2.y };
            mma16(acc[0][nt], ah[0], bh);
            mma16(acc[1][nt], ah[1], bh);
            mma16(acc[0][nt], ah[0], bl);
            mma16(acc[1][nt], ah[1], bl);
            mma16(acc[0][nt], al[0], bh);
            mma16(acc[1][nt], al[1], bh);
        }
        if (st < 14) PHI_STX((st + 2) % 3);
        __syncthreads();
    }

    // rowmax over 256 cols
#pragma unroll
    for (int mt = 0; mt < 2; mt++) {
        float mlo = -1e30f, mhi = -1e30f;
#pragma unroll
        for (int nt = 0; nt < 16; nt++) {
            mlo = fmaxf(mlo, fmaxf(acc[mt][nt][0], acc[mt][nt][1]));
            mhi = fmaxf(mhi, fmaxf(acc[mt][nt][2], acc[mt][nt][3]));
        }
        mlo = fmaxf(mlo, __shfl_xor_sync(0xffffffffu, mlo, 1));
        mlo = fmaxf(mlo, __shfl_xor_sync(0xffffffffu, mlo, 2));
        mhi = fmaxf(mhi, __shfl_xor_sync(0xffffffffu, mhi, 1));
        mhi = fmaxf(mhi, __shfl_xor_sync(0xffffffffu, mhi, 2));
        const int rl = wm * 32 + mt * 16 + gid;
        if (tig == 0) { rmax[wn * 128 + rl] = mlo; rmax[wn * 128 + rl + 8] = mhi; }
    }
    __syncthreads();

    // exp epilogue + (K-side) column-sum accumulation for fused zsum
    float zc0[16], zc1[16];
#pragma unroll
    for (int nt = 0; nt < 16; nt++) { zc0[nt] = 0.f; zc1[nt] = 0.f; }

#pragma unroll
    for (int mt = 0; mt < 2; mt++) {
        const int rl = wm * 32 + mt * 16 + gid, rh = rl + 8;
        const float Ml = fmaxf(rmax[rl], rmax[128 + rl]);
        const float Mh = fmaxf(rmax[rh], rmax[128 + rh]);
        float* pl = Phi + (row0 + rl) * MM;
        float* ph = Phi + (row0 + rh) * MM;
#pragma unroll
        for (int nt = 0; nt < 16; nt++) {
            const int col = wn * 128 + nt * 8 + tig * 2;
            float2 v0, v1;
            v0.x = tf32r(__expf(acc[mt][nt][0] - Ml) * 0.0625f);
            v0.y = tf32r(__expf(acc[mt][nt][1] - Ml) * 0.0625f);
            v1.x = tf32r(__expf(acc[mt][nt][2] - Mh) * 0.0625f);
            v1.y = tf32r(__expf(acc[mt][nt][3] - Mh) * 0.0625f);
            *(float2*)(pl + col) = v0;
            *(float2*)(ph + col) = v1;
            zc0[nt] += v0.x + v1.x;
            zc1[nt] += v0.y + v1.y;
        }
    }

    if (bid >= 256) {
#pragma unroll
        for (int nt = 0; nt < 16; nt++) {
            zc0[nt] += __shfl_xor_sync(0xffffffffu, zc0[nt], 4);
            zc0[nt] += __shfl_xor_sync(0xffffffffu, zc0[nt], 8);
            zc0[nt] += __shfl_xor_sync(0xffffffffu, zc0[nt], 16);
            zc1[nt] += __shfl_xor_sync(0xffffffffu, zc1[nt], 4);
            zc1[nt] += __shfl_xor_sync(0xffffffffu, zc1[nt], 8);
            zc1[nt] += __shfl_xor_sync(0xffffffffu, zc1[nt], 16);
            if (gid == 0) {
                const int col = wn * 128 + nt * 8 + tig * 2;
                zwp[wm * 256 + col]     = zc0[nt];
                zwp[wm * 256 + col + 1] = zc1[nt];
            }
        }
        __syncthreads();
        const float zz = zwp[tid] + zwp[256 + tid] + zwp[512 + tid] + zwp[768 + tid];
        g_z[(size_t)(bid - 256) * MM + tid] = zz;
    }
}

// ---------------------------------------------------------------------------
// Kernel 2: S_c[m][dv] = sum_k phiK[k][m] * V[k][dv], K=128 (4 stages of k32).
// ---------------------------------------------------------------------------
#define SC_SMEM ((2*4352 + 2*4352) * 4)

__global__ void __launch_bounds__(256) scontrib_mma(const float* __restrict__ V)
{
    extern __shared__ float sm[];
    float* As = sm;
    float* Bs = As + 8704;
    const uint32_t asb = su32(As), bsb = su32(Bs);

    const int tid = threadIdx.x;
    const int lane = tid & 31, w = tid >> 5;
    const int gid = lane >> 2, tig = lane & 3;
    const int wm = w >> 1, wn = w & 1;

    const int bc = blockIdx.z;
    const int m0c = blockIdx.y * 128, dv0 = blockIdx.x * 128;
    const size_t base = (size_t)(bc >> 5) * SEQ + (size_t)(bc & 31) * CHUNK;
    const float* pk = g_phiK + base * MM + m0c;
    const float* vv = V + base * DVV + dv0;

    float acc[2][8][4];
#pragma unroll
    for (int mt = 0; mt < 2; mt++)
#pragma unroll
        for (int nt = 0; nt < 8; nt++)
#pragma unroll
            for (int i = 0; i < 4; i++) acc[mt][nt][i] = 0.f;

#define SC_CP(st, bf) { \
    _Pragma("unroll") \
    for (int j = 0; j < 4; j++) { \
        const int idx = tid + j * 256; \
        const int r = idx >> 5, q = (idx & 31) * 4; \
        cpa(asb + ((bf) * 4352 + r * 136 + q) * 4, pk + ((st) * 32 + r) * MM + q); \
        cpa(bsb + ((bf) * 4352 + r * 136 + q) * 4, vv + ((st) * 32 + r) * DVV + q); \
    } \
    CP_COMMIT(); }

    SC_CP(0, 0);
#pragma unroll 1
    for (int st = 0; st < 4; st++) {
        const int buf = st & 1;
        if (st < 3) { SC_CP(st + 1, buf ^ 1); CP_WAIT1(); } else { CP_WAIT0(); }
        __syncthreads();
        const float* as = As + buf * 4352;
        const float* bs = Bs + buf * 4352;
#pragma unroll
        for (int k8 = 0; k8 < 32; k8 += 8) {
            uint32_t a[2][4];
#pragma unroll
            for (int mt = 0; mt < 2; mt++) {
                const int rb = wm * 32 + mt * 16;
                a[mt][0] = fb(as[(k8 + tig) * 136 + rb + gid]);
                a[mt][1] = fb(as[(k8 + tig) * 136 + rb + gid + 8]);
                a[mt][2] = fb(as[(k8 + tig + 4) * 136 + rb + gid]);
                a[mt][3] = fb(as[(k8 + tig + 4) * 136 + rb + gid + 8]);
            }
#pragma unroll
            for (int nt = 0; nt < 8; nt++) {
                const int nb = wn * 64 + nt * 8;
                uint32_t b[2] = { fb(bs[(k8 + tig) * 136 + nb + gid]),
                                  fb(bs[(k8 + tig + 4) * 136 + nb + gid]) };
                mma8(acc[0][nt], a[0], b);
                mma8(acc[1][nt], a[1], b);
            }
        }
        __syncthreads();
    }

    float* sout = g_S + (size_t)bc * (MM * DVV);
#pragma unroll
    for (int mt = 0; mt < 2; mt++) {
        const int m = m0c + wm * 32 + mt * 16 + gid;
#pragma unroll
        for (int nt = 0; nt < 8; nt++) {
            const int col = dv0 + wn * 64 + nt * 8 + tig * 2;
            *(float2*)(sout + (size_t)m * DVV + col) =
                make_float2(acc[mt][nt][0], acc[mt][nt][1]);
            *(float2*)(sout + (size_t)(m + 8) * DVV + col) =
                make_float2(acc[mt][nt][2], acc[mt][nt][3]);
        }
    }
}

// exclusive prefixes over chunks
__global__ void __launch_bounds__(256) prefixS_kernel()
{
    const size_t g = (size_t)blockIdx.x * 256 + threadIdx.x;
    const size_t b = g >> 16, r = g & 65535;
    float* p = g_S + b * (size_t)NCHUNK * 65536 + r;
    float v[NCHUNK];
#pragma unroll
    for (int c = 0; c < NCHUNK; c++) v[c] = p[(size_t)c * 65536];
    float run = 0.f;
#pragma unroll
    for (int c = 0; c < NCHUNK; c++) { float t = v[c]; v[c] = run; run += t; }
#pragma unroll
    for (int c = 0; c < NCHUNK; c++) p[(size_t)c * 65536] = v[c];
}
__global__ void __launch_bounds__(256) prefixz_kernel()
{
    const int g = blockIdx.x * 256 + threadIdx.x;
    const int b = g / MM, m = g % MM;
    float* p = g_z + (size_t)b * NCHUNK * MM + m;
    float v[NCHUNK];
#pragma unroll
    for (int c = 0; c < NCHUNK; c++) v[c] = p[c * MM];
    float run = 0.f;
#pragma unroll
    for (int c = 0; c < NCHUNK; c++) { float t = v[c]; v[c] = run; run += t; }
#pragma unroll
    for (int c = 0; c < NCHUNK; c++) p[c * MM] = v[c];
}

// ---------------------------------------------------------------------------
// Kernel 3 (FUSED): per (b,chunk), depth-3 pipelines:
//   Merged Phase A+I over K=256 (shared phiQ tiles):
//     acc  = Pq Pk^T;  acc2 = Pq S_pre;  dp = den_inter FMAs
//   Epilogue: mask/round acc -> As2, rowsum -> rsh.
//   Phase B: acc2 += As2 @ V (K=128).   Out = acc2 / den.
// ---------------------------------------------------------------------------
#define CH_SMEM ((3*2560 + 3*2560 + 3*4224 + 16896 + 256 + 256 + 256 + 128) * 4)

__global__ void __launch_bounds__(256) chunk_fused(const float* __restrict__ V,
                                                   float* __restrict__ Out)
{
    extern __shared__ float sm[];
    float* Aq  = sm;              // 3*128*20 (phiQ tiles)
    float* Kk  = Aq + 7680;       // 3*128*20 (phiK tiles)
    float* Sp  = Kk + 7680;       // 3*16*264 (Spre tiles; later V tiles)
    float* As2 = Sp + 12672;      // 128*132
    float* zsm = As2 + 16896;     // 256
    float* rsh = zsm + 256;       // 256
    float* dps = rsh + 256;       // 256
    float* rden = dps + 256;      // 128
    const uint32_t aqb = su32(Aq), kkb = su32(Kk), spb = su32(Sp);

    const int tid = threadIdx.x;
    const int lane = tid & 31, w = tid >> 5;
    const int gid = lane >> 2, tig = lane & 3;
    const int wm = w >> 1, wn = w & 1;

    const int bc = blockIdx.x;
    const size_t base = (size_t)(bc >> 5) * SEQ + (size_t)(bc & 31) * CHUNK;
    const float* pq = g_phiQ + base * MM;
    const float* pk = g_phiK + base * MM;
    const float* Vb = V + base * DVV;
    const float* sS = g_S + (size_t)bc * (MM * DVV);

    zsm[tid] = g_z[(size_t)bc * MM + tid];

    float acc[2][8][4];
    float acc2[2][16][4];
#pragma unroll
    for (int mt = 0; mt < 2; mt++) {
#pragma unroll
        for (int nt = 0; nt < 8; nt++)
#pragma unroll
            for (int i = 0; i < 4; i++) acc[mt][nt][i] = 0.f;
#pragma unroll
        for (int nt = 0; nt < 16; nt++)
#pragma unroll
            for (int i = 0; i < 4; i++) acc2[mt][nt][i] = 0.f;
    }

#define CAI_CP(st, bf) { \
    _Pragma("unroll") \
    for (int j = 0; j < 2; j++) { \
        const int idx = tid + j * 256; \
        const int r = idx >> 2, q = (idx & 3) * 4; \
        cpa(aqb + ((bf) * 2560 + r * 20 + q) * 4, pq + r * MM + (st) * 16 + q); \
        cpa(kkb + ((bf) * 2560 + r * 20 + q) * 4, pk + r * MM + (st) * 16 + q); \
    } \
    _Pragma("unroll") \
    for (int j = 0; j < 4; j++) { \
        const int idx = tid + j * 256; \
        const int r = idx >> 6, qc = (idx & 63) * 4; \
        cpa(spb + ((bf) * 4224 + r * 264 + qc) * 4, sS + ((st) * 16 + r) * DVV + qc); \
    } \
    CP_COMMIT(); }

    float dp = 0.f;
    const int dr = tid >> 1, dh = tid & 1;

    CAI_CP(0, 0);
    CAI_CP(1, 1);
#pragma unroll 1
    for (int st = 0; st < 16; st++) {
        const int buf = st % 3;
        if (st < 14) { CAI_CP(st + 2, (st + 2) % 3); CP_WAIT2(); }
        else if (st == 14) { CP_WAIT1(); }
        else { CP_WAIT0(); }
        __syncthreads();
        const float* aq = Aq + buf * 2560;
        const float* kk = Kk + buf * 2560;
        const float* sp = Sp + buf * 4224;
#pragma unroll
        for (int k8 = 0; k8 < 16; k8 += 8) {
            uint32_t a[2][4];
#pragma unroll
            for (int mt = 0; mt < 2; mt++) {
                const int rb = wm * 32 + mt * 16;
                a[mt][0] = fb(aq[(rb + gid) * 20 + k8 + tig]);
                a[mt][1] = fb(aq[(rb + gid + 8) * 20 + k8 + tig]);
                a[mt][2] = fb(aq[(rb + gid) * 20 + k8 + tig + 4]);
                a[mt][3] = fb(aq[(rb + gid + 8) * 20 + k8 + tig + 4]);
            }
#pragma unroll
            for (int nt = 0; nt < 8; nt++) {
                const int nb = wn * 64 + nt * 8;
                uint32_t b[2] = { fb(kk[(nb + gid) * 20 + k8 + tig]),
                                  fb(kk[(nb + gid) * 20 + k8 + tig + 4]) };
                mma8(acc[0][nt], a[0], b);
                mma8(acc[1][nt], a[1], b);
            }
#pragma unroll
            for (int nt = 0; nt < 16; nt++) {
                const int nb = wn * 128 + nt * 8;
                uint32_t b[2] = { fb(sp[(k8 + tig) * 264 + nb + gid]),
                                  fb(sp[(k8 + tig + 4) * 264 + nb + gid]) };
                mma8(acc2[0][nt], a[0], b);
                mma8(acc2[1][nt], a[1], b);
            }
        }
#pragma unroll
        for (int j = 0; j < 8; j++)
            dp = fmaf(aq[dr * 20 + dh * 8 + j], zsm[st * 16 + dh * 8 + j], dp);
        __syncthreads();
    }
    dps[tid] = dp;

#define CB_CP(st, bf) { \
    _Pragma("unroll") \
    for (int j = 0; j < 4; j++) { \
        const int idx = tid + j * 256; \
        const int r = idx >> 6, qc = (idx & 63) * 4; \
        cpa(spb + ((bf) * 4224 + r * 264 + qc) * 4, Vb + ((st) * 16 + r) * DVV + qc); \
    } \
    CP_COMMIT(); }

    CB_CP(0, 0);
    CB_CP(1, 1);

#pragma unroll
    for (int mt = 0; mt < 2; mt++) {
        const int row = wm * 32 + mt * 16 + gid, row2 = row + 8;
        float rs1 = 0.f, rs2 = 0.f;
#pragma unroll
        for (int nt = 0; nt < 8; nt++) {
            const int col = wn * 64 + nt * 8 + tig * 2;
            float v0 = (col     <= row)  ? tf32r(acc[mt][nt][0]) : 0.f;
            float v1 = (col + 1 <= row)  ? tf32r(acc[mt][nt][1]) : 0.f;
            float v2 = (col     <= row2) ? tf32r(acc[mt][nt][2]) : 0.f;
            float v3 = (col + 1 <= row2) ? tf32r(acc[mt][nt][3]) : 0.f;
            rs1 += v0 + v1; rs2 += v2 + v3;
            *(float2*)(As2 + row * 132 + col) = make_float2(v0, v1);
            *(float2*)(As2 + row2 * 132 + col) = make_float2(v2, v3);
        }
        rs1 += __shfl_xor_sync(0xffffffffu, rs1, 1);
        rs1 += __shfl_xor_sync(0xffffffffu, rs1, 2);
        rs2 += __shfl_xor_sync(0xffffffffu, rs2, 1);
        rs2 += __shfl_xor_sync(0xffffffffu, rs2, 2);
        if (tig == 0) { rsh[wn * 128 + row] = rs1; rsh[wn * 128 + row2] = rs2; }
    }
    __syncthreads();
    if (tid < 128)
        rden[tid] = 1.f / fmaxf(rsh[tid] + rsh[128 + tid] + dps[2 * tid] + dps[2 * tid + 1], 1e-6f);

#pragma unroll 1
    for (int st = 0; st < 8; st++) {
        const int buf = st % 3;
        if (st < 6) { CB_CP(st + 2, (st + 2) % 3); CP_WAIT2(); }
        else if (st == 6) { CP_WAIT1(); }
        else { CP_WAIT0(); }
        __syncthreads();
        const float* vs = Sp + buf * 4224;
#pragma unroll
        for (int k8 = 0; k8 < 16; k8 += 8) {
            const int kg = st * 16 + k8;
            uint32_t a[2][4];
#pragma unroll
            for (int mt = 0; mt < 2; mt++) {
                const int rb = wm * 32 + mt * 16;
                a[mt][0] = fb(As2[(rb + gid) * 132 + kg + tig]);
                a[mt][1] = fb(As2[(rb + gid + 8) * 132 + kg + tig]);
                a[mt][2] = fb(As2[(rb + gid) * 132 + kg + tig + 4]);
                a[mt][3] = fb(As2[(rb + gid + 8) * 132 + kg + tig + 4]);
            }
#pragma unroll
            for (int nt = 0; nt < 16; nt++) {
                const int nb = wn * 128 + nt * 8;
                uint32_t b[2] = { fb(vs[(k8 + tig) * 264 + nb + gid]),
                                  fb(vs[(k8 + tig + 4) * 264 + nb + gid]) };
                mma8(acc2[0][nt], a[0], b);
                mma8(acc2[1][nt], a[1], b);
            }
        }
        __syncthreads();
    }

#pragma unroll
    for (int mt = 0; mt < 2; mt++) {
        const int t = wm * 32 + mt * 16 + gid, t2 = t + 8;
        const float r1 = rden[t], r2 = rden[t2];
#pragma unroll
        for (int nt = 0; nt < 16; nt++) {
            const int col = wn * 128 + nt * 8 + tig * 2;
            *(float2*)(Out + (base + t) * DVV + col) =
                make_float2(acc2[mt][nt][0] * r1, acc2[mt][nt][1] * r1);
            *(float2*)(Out + (base + t2) * DVV + col) =
                make_float2(acc2[mt][nt][2] * r2, acc2[mt][nt][3] * r2);
        }
    }
}

// ---------------------------------------------------------------------------
extern "C" void kernel_launch(void* const* d_in, const int* in_sizes, int n_in,
                              void* d_out, int out_size)
{
    (void)in_sizes; (void)n_in; (void)out_size;
    const float* Q   = (const float*)d_in[0];
    const float* Kin = (const float*)d_in[1];
    const float* V   = (const float*)d_in[2];
    const float* W   = (const float*)d_in[3];
    float* Out = (float*)d_out;

    cudaFuncSetAttribute(phi_mma,      cudaFuncAttributeMaxDynamicSharedMemorySize, PHI_SMEM);
    cudaFuncSetAttribute(scontrib_mma, cudaFuncAttributeMaxDynamicSharedMemorySize, SC_SMEM);
    cudaFuncSetAttribute(chunk_fused,  cudaFuncAttributeMaxDynamicSharedMemorySize, CH_SMEM);

    wsplit<<<16, 256>>>(W);
    phi_mma<<<512, 256, PHI_SMEM>>>(Q, Kin);
    prefixz_kernel<<<(BATCH * MM) / 256, 256>>>();
    scontrib_mma<<<dim3(2, 2, BATCH * NCHUNK), 256, SC_SMEM>>>(V);
    prefixS_kernel<<<(BATCH * MM * DVV) / 256, 256>>>();
    chunk_fused<<<BATCH * NCHUNK, 256, CH_SMEM>>>(V, Out);
}